// round 2
// baseline (speedup 1.0000x reference)
#include <cuda_runtime.h>
#include <cstdint>

// NGram gather: in (B=8, S=2048, E=512) f32 -> out (B=8, N=5, S=2048, E=512)
// out[b,k,s,e] = in[b, s+k-2, e] if 0 <= s+k-2 < S else 0
//
// Pure bandwidth problem: 32MB read (L2-resident after first touch) + 160MB write.
// One float4 per thread, fully coalesced.

static constexpr int B = 8;
static constexpr int S = 2048;
static constexpr int E = 512;
static constexpr int NG = 5;          // gram width
static constexpr int LEFT = 2;        // (NG-1)/2
static constexpr int E4 = E / 4;      // 128 float4 per row

// total float4s in output: B * NG * S * E4 = 8*5*2048*128 = 10,485,760 (fits in int32)
static constexpr int TOTAL4 = B * NG * S * E4;

__global__ __launch_bounds__(256) void ngram_kernel(const float4* __restrict__ in,
                                                    float4* __restrict__ out) {
    int idx = blockIdx.x * blockDim.x + threadIdx.x;
    if (idx >= TOTAL4) return;

    int e4 = idx & (E4 - 1);        // E4 = 128, power of 2
    int t  = idx >> 7;              // / E4
    int s  = t & (S - 1);           // S = 2048, power of 2
    t >>= 11;                       // / S  -> t = b*NG + k, range [0, 40)
    int k  = t % NG;
    int b  = t / NG;

    int src_s = s + k - LEFT;
    float4 v = make_float4(0.f, 0.f, 0.f, 0.f);
    if ((unsigned)src_s < (unsigned)S) {
        v = in[(b * S + src_s) * E4 + e4];
    }
    out[idx] = v;
}

extern "C" void kernel_launch(void* const* d_in, const int* in_sizes, int n_in,
                              void* d_out, int out_size) {
    const float4* in = (const float4*)d_in[0];
    float4* out = (float4*)d_out;

    const int threads = 256;
    const int blocks = (TOTAL4 + threads - 1) / threads;  // 40960
    ngram_kernel<<<blocks, threads>>>(in, out);
}

// round 3
// speedup vs baseline: 1.0661x; 1.0661x over previous
#include <cuda_runtime.h>
#include <cstdint>

// NGram gather: in (B=8, S=2048, E=512) f32 -> out (B=8, N=5, S=2048, E=512)
// out[b,k,s,e] = in[b, s+k-2, e] if 0 <= s+k-2 < S else 0
//
// Scatter formulation: each thread reads ONE input float4 and stores it to the
// 5 output positions out[b, k, s_in+2-k] (predicated on range). This cuts read
// traffic 5x vs the gather formulation. Border rows (where the source would be
// out of range) are zero-filled by a tiny second kernel on disjoint addresses.

static constexpr int B = 8;
static constexpr int S = 2048;
static constexpr int E = 512;
static constexpr int NG = 5;
static constexpr int E4 = E / 4;                 // 128 float4 per row
static constexpr int IN4 = B * S * E4;           // 2,097,152 input float4s

__global__ __launch_bounds__(256) void ngram_scatter(const float4* __restrict__ in,
                                                     float4* __restrict__ out) {
    int idx = blockIdx.x * blockDim.x + threadIdx.x;   // exact grid, no guard needed
    int e4 = idx & (E4 - 1);
    int t  = idx >> 7;            // / E4
    int s  = t & (S - 1);
    int b  = t >> 11;             // / S

    float4 v = in[idx];

    // out[b, k, s + 2 - k, e4] for k = 0..4 (independent, predicated stores)
    int base = b * NG;            // plane index of (b, k=0)
#pragma unroll
    for (int k = 0; k < NG; k++) {
        int s_out = s + 2 - k;
        if ((unsigned)s_out < (unsigned)S) {
            __stcs(&out[((base + k) * S + s_out) * E4 + e4], v);
        }
    }
}

// Border rows with no source: per b — (k=0,s=0),(k=0,s=1),(k=1,s=0),
// (k=3,s=S-1),(k=4,s=S-2),(k=4,s=S-1). 48 rows x 128 float4 = 6144 threads.
__constant__ int c_k[6] = {0, 0, 1, 3, 4, 4};
__constant__ int c_s[6] = {0, 1, 0, S - 1, S - 2, S - 1};

__global__ __launch_bounds__(128) void ngram_zero_border(float4* __restrict__ out) {
    int e4 = threadIdx.x;                 // 128 threads = one row
    int r  = blockIdx.x;                  // 0..47
    int b  = r / 6;
    int j  = r - b * 6;
    int k  = c_k[j];
    int s  = c_s[j];
    out[((b * NG + k) * S + s) * E4 + e4] = make_float4(0.f, 0.f, 0.f, 0.f);
}

extern "C" void kernel_launch(void* const* d_in, const int* in_sizes, int n_in,
                              void* d_out, int out_size) {
    const float4* in = (const float4*)d_in[0];
    float4* out = (float4*)d_out;

    ngram_scatter<<<IN4 / 256, 256>>>(in, out);     // 8192 blocks
    ngram_zero_border<<<B * 6, 128>>>(out);          // disjoint addresses, any order
}

// round 5
// speedup vs baseline: 1.1338x; 1.0635x over previous
#include <cuda_runtime.h>
#include <cstdint>

// NGram gather: in (B=8, S=2048, E=512) f32 -> out (B=8, N=5, S=2048, E=512)
// out[b,k,s,e] = in[b, s+k-2, e] if 0 <= s+k-2 < S else 0
//
// Scatter formulation: each thread reads ONE input float4 and stores it to the
// 5 output positions out[b, k, s_in+2-k] (predicated on range) -> read traffic
// is 1x (32MB) instead of 5x. Border rows that have no source are zero-filled
// by the s==0 threads of each (b, e4) — folded into the same launch to avoid
// a second kernel's ~3.6us launch/drain overhead (measured in R3).

static constexpr int B = 8;
static constexpr int S = 2048;
static constexpr int E = 512;
static constexpr int NG = 5;
static constexpr int E4 = E / 4;                 // 128 float4 per row
static constexpr int IN4 = B * S * E4;           // 2,097,152 input float4s

__global__ __launch_bounds__(256) void ngram_scatter(const float4* __restrict__ in,
                                                     float4* __restrict__ out) {
    int idx = blockIdx.x * blockDim.x + threadIdx.x;   // exact grid, no tail
    int e4 = idx & (E4 - 1);
    int t  = idx >> 7;            // / E4
    int s  = t & (S - 1);
    int b  = t >> 11;             // / S

    float4 v = in[idx];

    // out[b, k, s + 2 - k, e4] for k = 0..4 (independent, predicated stores)
    int base = b * NG;            // plane index of (b, k=0)
#pragma unroll
    for (int k = 0; k < NG; k++) {
        int s_out = s + 2 - k;
        if ((unsigned)s_out < (unsigned)S) {
            __stcs(&out[((base + k) * S + s_out) * E4 + e4], v);
        }
    }

    // Border zero-fill: rows (k,s) with no source, 6 per batch:
    // (0,0) (0,1) (1,0) (3,S-1) (4,S-2) (4,S-1).
    // Done by the s==0 threads (whole warps, uniform branch, coalesced stores).
    if (s == 0) {
        const float4 z = make_float4(0.f, 0.f, 0.f, 0.f);
        __stcs(&out[((base + 0) * S + 0      ) * E4 + e4], z);
        __stcs(&out[((base + 0) * S + 1      ) * E4 + e4], z);
        __stcs(&out[((base + 1) * S + 0      ) * E4 + e4], z);
        __stcs(&out[((base + 3) * S + (S - 1)) * E4 + e4], z);
        __stcs(&out[((base + 4) * S + (S - 2)) * E4 + e4], z);
        __stcs(&out[((base + 4) * S + (S - 1)) * E4 + e4], z);
    }
}

extern "C" void kernel_launch(void* const* d_in, const int* in_sizes, int n_in,
                              void* d_out, int out_size) {
    const float4* in = (const float4*)d_in[0];
    float4* out = (float4*)d_out;

    ngram_scatter<<<IN4 / 256, 256>>>(in, out);     // 8192 blocks x 256 threads
}